// round 9
// baseline (speedup 1.0000x reference)
#include <cuda_runtime.h>
#include <cuda_fp16.h>
#include <math.h>
#include <stdint.h>

#define Bq    32
#define Nn    1024
#define Dd    768
#define E_TOK 4
#define E_CH  4
#define Ee    8
#define HN    4096
#define HD    3072

#define SLOT_STRIDE 3145728   // 768*4096 == 1024*3072

// ---------------- scratch (__device__ globals: sanctioned scratch path) -----
__device__ float g_pmean[Bq * 32 * Dd];   // per-(b, n-chunk) partial column sums
__device__ float g_xmean[Bq * Dd];
__device__ float g_combine[Bq * Ee];
__device__ int   g_slot[Bq * Ee];
__device__ int   g_wl[Bq * 2];            // compact work list: (b<<8)|eg

__device__ __half g_xt [(size_t)Bq * Dd * Nn];
__device__ __half g_xc [(size_t)Bq * Nn * Dd];
__device__ __half g_w1t[(size_t)E_TOK * HN * Nn];
__device__ __half g_w2t[(size_t)E_TOK * Nn * HN];
__device__ __half g_w1c[(size_t)E_CH * HD * Dd];
__device__ __half g_w2c[(size_t)E_CH * Dd * HD];
__device__ __half g_hid[(size_t)Bq * 2 * SLOT_STRIDE];

// ---------------- smem geometry ---------------------------------------------
#define BM 128
#define BN 128
#define BK 64
#define SKB 144
#define A_BYTES (BM * SKB)
#define B_BYTES (BN * SKB)
#define ST_BYTES (A_BYTES + B_BYTES)   // 36864
#define NSTAGE 3
#define SMEM_DYN (NSTAGE * ST_BYTES)   // 110592

// ---------------- PTX helpers ------------------------------------------------
__device__ __forceinline__ uint32_t s2u(const void* p) {
    uint32_t a;
    asm("{ .reg .u64 t; cvta.to.shared.u64 t, %1; cvt.u32.u64 %0, t; }" : "=r"(a) : "l"(p));
    return a;
}
__device__ __forceinline__ void cp16(uint32_t sdst, const void* g) {
    asm volatile("cp.async.cg.shared.global [%0], [%1], 16;" :: "r"(sdst), "l"(g));
}
__device__ __forceinline__ void cp_commit() { asm volatile("cp.async.commit_group;" ::: "memory"); }
__device__ __forceinline__ void cp_wait1() { asm volatile("cp.async.wait_group 1;" ::: "memory"); }
__device__ __forceinline__ void cp_wait0() { asm volatile("cp.async.wait_group 0;" ::: "memory"); }
__device__ __forceinline__ void ldsm4(uint32_t* r, uint32_t addr) {
    asm volatile("ldmatrix.sync.aligned.m8n8.x4.shared.b16 {%0,%1,%2,%3}, [%4];"
                 : "=r"(r[0]), "=r"(r[1]), "=r"(r[2]), "=r"(r[3]) : "r"(addr));
}
__device__ __forceinline__ void mma_f16(float* c, const uint32_t* a, const uint32_t* b) {
    asm volatile(
        "mma.sync.aligned.m16n8k16.row.col.f32.f16.f16.f32 "
        "{%0,%1,%2,%3}, {%4,%5,%6,%7}, {%8,%9}, {%0,%1,%2,%3};"
        : "+f"(c[0]), "+f"(c[1]), "+f"(c[2]), "+f"(c[3])
        : "r"(a[0]), "r"(a[1]), "r"(a[2]), "r"(a[3]), "r"(b[0]), "r"(b[1]));
}
__device__ __forceinline__ void stcs_u16(__half* p, __half v) {
    unsigned short u = *reinterpret_cast<unsigned short*>(&v);
    asm volatile("st.global.cs.u16 [%0], %1;" :: "l"(p), "h"(u) : "memory");
}
__device__ __forceinline__ void stcs_u32(void* p, uint32_t v) {
    asm volatile("st.global.cs.u32 [%0], %1;" :: "l"(p), "r"(v) : "memory");
}
__device__ __forceinline__ void stcs_v2u32(void* p, uint32_t a, uint32_t b) {
    asm volatile("st.global.cs.v2.u32 [%0], {%1, %2};" :: "l"(p), "r"(a), "r"(b) : "memory");
}
__device__ __forceinline__ void stcs_v2f32(void* p, float a, float b) {
    asm volatile("st.global.cs.v2.f32 [%0], {%1, %2};" :: "l"(p), "f"(a), "f"(b) : "memory");
}
__device__ __forceinline__ float gelu_tanh(float v) {
    float c = 0.7978845608028654f * (v + 0.044715f * v * v * v);
    return 0.5f * v * (1.0f + tanhf(c));
}

// ---------------- GEMM core (validated, unchanged) ---------------------------
template <int R>
__device__ __forceinline__ void cpa_tile(uint32_t sdst, const __half* __restrict__ g,
                                         int k0, int strideK, int tid) {
    #pragma unroll
    for (int i = 0; i < R * 8 / 256; i++) {
        int c = tid + i * 256;
        int row = c >> 3, seg = c & 7;
        cp16(sdst + row * SKB + seg * 16,
             g + (size_t)row * strideK + k0 + seg * 8);
    }
}

__device__ __forceinline__ void issue_stage(uint32_t sbase,
                                            const __half* A, const __half* B,
                                            int k0, int strideK, int tid) {
    cpa_tile<BM>(sbase, A, k0, strideK, tid);
    cpa_tile<BN>(sbase + A_BYTES, B, k0, strideK, tid);
    cp_commit();
}

__device__ __forceinline__ void compute_stage(uint32_t s, float acc[4][4][4],
                                              int wm, int wn, int lane) {
    uint32_t aRow = lane & 15;
    uint32_t aK   = (lane >> 4) * 8;
    uint32_t bRow = (lane & 7) + ((lane >> 4) & 1) * 8;
    uint32_t bK   = ((lane >> 3) & 1) * 8;
    uint32_t sA = s, sB = s + A_BYTES;
    #pragma unroll
    for (int ks = 0; ks < 4; ks++) {
        uint32_t b[4][2];
        #pragma unroll
        for (int q = 0; q < 2; q++) {
            uint32_t t[4];
            ldsm4(t, sB + (wn * 32 + q * 16 + bRow) * SKB + (ks * 16 + bK) * 2);
            b[q * 2][0] = t[0]; b[q * 2][1] = t[1];
            b[q * 2 + 1][0] = t[2]; b[q * 2 + 1][1] = t[3];
        }
        #pragma unroll
        for (int mf = 0; mf < 4; mf++) {
            uint32_t a[4];
            ldsm4(a, sA + (wm * 64 + mf * 16 + aRow) * SKB + (ks * 16 + aK) * 2);
            #pragma unroll
            for (int nf = 0; nf < 4; nf++)
                mma_f16(acc[mf][nf], a, b[nf]);
        }
    }
}

__device__ __forceinline__ void gemm_pipeline(uint32_t sb,
                                              const __half* A, const __half* B, int K,
                                              float acc[4][4][4],
                                              int wm, int wn, int lane, int tid) {
    int nch = K / BK;
    issue_stage(sb,            A, B, 0,  K, tid);
    issue_stage(sb + ST_BYTES, A, B, BK, K, tid);
    for (int c = 0; c < nch; c++) {
        if (c + 1 < nch) cp_wait1(); else cp_wait0();
        __syncthreads();
        compute_stage(sb + (c % 3) * ST_BYTES, acc, wm, wn, lane);
        if (c + 2 < nch)
            issue_stage(sb + ((c + 2) % 3) * ST_BYTES, A, B, (c + 2) * BK, K, tid);
    }
    __syncthreads();
}

// ---------------- launch 1: fused x conversion + mean partials ---------------
__global__ void xcvt_mean_kernel(const float* __restrict__ x) {
    __shared__ float t[32][33];
    __shared__ float ps[8][32];
    int b = blockIdx.z;
    int d0 = blockIdx.x * 32, n0 = blockIdx.y * 32;
    int tx = threadIdx.x, ty = threadIdx.y;
    const float* xb = x + (size_t)b * Nn * Dd;
    size_t cbase = (size_t)b * Nn * Dd;
    float part = 0.f;
    #pragma unroll
    for (int k = 0; k < 32; k += 8) {
        float v = xb[(size_t)(n0 + ty + k) * Dd + d0 + tx];
        t[ty + k][tx] = v;
        part += v;
        stcs_u16(g_xc + cbase + (size_t)(n0 + ty + k) * Dd + d0 + tx, __float2half_rn(v));
    }
    ps[ty][tx] = part;
    __syncthreads();
    size_t base = (size_t)b * Dd * Nn;
    #pragma unroll
    for (int k = 0; k < 32; k += 8)
        stcs_u16(g_xt + base + (size_t)(d0 + ty + k) * Nn + n0 + tx,
                 __float2half_rn(t[tx][ty + k]));
    if (ty == 0) {
        float s = 0.f;
        #pragma unroll
        for (int j = 0; j < 8; j++) s += ps[j][tx];
        g_pmean[((size_t)b * 32 + blockIdx.y) * Dd + d0 + tx] = s;
    }
}

// ---------------- launch 2: fused mean-reduce + gate + work list -------------
__global__ void gate_kernel(const float* __restrict__ rw, float* __restrict__ aux_out) {
    // phase 1: finish the mean (single block; fixed order -> deterministic)
    for (int i = threadIdx.x; i < Bq * Dd; i += blockDim.x) {
        int b = i / Dd, d = i % Dd;
        float s = 0.f;
        #pragma unroll 8
        for (int c = 0; c < 32; c++) s += g_pmean[((size_t)b * 32 + c) * Dd + d];
        g_xmean[i] = s * (1.0f / Nn);
    }
    __syncthreads();   // block-scope global visibility

    __shared__ float s_probs[Bq][Ee];
    __shared__ int   s_top1[Bq];
    __shared__ int   s_top2[Bq];
    int warp = threadIdx.x >> 5, lane = threadIdx.x & 31;
    int nwarp = blockDim.x >> 5;
    for (int b = warp; b < Bq; b += nwarp) {
        float logits[Ee];
        #pragma unroll
        for (int e = 0; e < Ee; e++) {
            float s = 0.f;
            for (int d = lane; d < Dd; d += 32)
                s += g_xmean[b * Dd + d] * rw[e * Dd + d];
            #pragma unroll
            for (int o = 16; o; o >>= 1) s += __shfl_xor_sync(0xffffffffu, s, o);
            logits[e] = s;
        }
        if (lane == 0) {
            float mx = logits[0];
            #pragma unroll
            for (int e = 1; e < Ee; e++) mx = fmaxf(mx, logits[e]);
            float p[Ee], se = 0.f;
            #pragma unroll
            for (int e = 0; e < Ee; e++) { p[e] = expf(logits[e] - mx); se += p[e]; }
            float inv = 1.0f / se;
            #pragma unroll
            for (int e = 0; e < Ee; e++) p[e] *= inv;
            int i0 = 0;
            #pragma unroll
            for (int e = 1; e < Ee; e++) if (p[e] > p[i0]) i0 = e;
            int i1 = (i0 == 0) ? 1 : 0;
            #pragma unroll
            for (int e = 0; e < Ee; e++) if (e != i1 && e != i0 && p[e] > p[i1]) i1 = e;
            float ws = p[i0] + p[i1];
            #pragma unroll
            for (int e = 0; e < Ee; e++) { g_combine[b * Ee + e] = 0.f; g_slot[b * Ee + e] = -1; }
            g_combine[b * Ee + i0] = p[i0] / ws;  g_slot[b * Ee + i0] = b * 2;
            g_combine[b * Ee + i1] = p[i1] / ws;  g_slot[b * Ee + i1] = b * 2 + 1;
            #pragma unroll
            for (int e = 0; e < Ee; e++) s_probs[b][e] = p[e];
            s_top1[b] = i0;
            s_top2[b] = i1;
        }
    }
    __syncthreads();
    if (threadIdx.x == 0) {
        int cnt = 0;
        for (int b = 0; b < Bq; b++)
            for (int e = 0; e < Ee; e++)
                if (e == s_top1[b] || e == s_top2[b]) g_wl[cnt++] = (b << 8) | e;
        if (aux_out != nullptr) {
            float aux = 0.f;
            for (int e = 0; e < Ee; e++) {
                float pm = 0.f; int c = 0;
                for (int b = 0; b < Bq; b++) { pm += s_probs[b][e]; c += (s_top1[b] == e); }
                aux += (pm / Bq) * ((float)c / Bq);
            }
            aux_out[0] = (float)Ee * aux;
        }
    }
}

// ---------------- launch 3: all weight conversions ---------------------------
#define N4_TW (E_TOK * HN * Nn / 4)
#define N4_CW (E_CH * HD * Dd / 4)
__global__ void cvt_all_kernel(const float* __restrict__ tok_w1, const float* __restrict__ tok_w2,
                               const float* __restrict__ ch_w1,  const float* __restrict__ ch_w2,
                               __half* __restrict__ o1, __half* __restrict__ o2,
                               __half* __restrict__ o3, __half* __restrict__ o4) {
    int i = blockIdx.x * blockDim.x + threadIdx.x;
    const float* in; __half* out; int idx;
    if (i < N4_TW)                    { in = tok_w1; out = o1; idx = i; }
    else if (i < 2 * N4_TW)           { in = tok_w2; out = o2; idx = i - N4_TW; }
    else if (i < 2 * N4_TW + N4_CW)   { in = ch_w1;  out = o3; idx = i - 2 * N4_TW; }
    else if (i < 2 * (N4_TW + N4_CW)) { in = ch_w2;  out = o4; idx = i - 2 * N4_TW - N4_CW; }
    else return;
    float4 v = ((const float4*)in)[idx];
    __half2 h0 = __floats2half2_rn(v.x, v.y);
    __half2 h1 = __floats2half2_rn(v.z, v.w);
    stcs_v2u32((char*)out + 8 * (size_t)idx,
               *reinterpret_cast<uint32_t*>(&h0), *reinterpret_cast<uint32_t*>(&h1));
}

// ---------------- launch 4 (ncu-captured): GEMM1 -----------------------------
__global__ void __launch_bounds__(256, 2) gemm1_mma(const float* __restrict__ tok_b1,
                                                    const float* __restrict__ ch_b1) {
    extern __shared__ char smem[];
    int code = g_wl[blockIdx.y];
    int b = code >> 8, eg = code & 255;
    int is_token = (eg < E_TOK);
    int el = is_token ? eg : (eg - E_TOK);
    float w = g_combine[b * Ee + eg];
    int slot = g_slot[b * Ee + eg];
    int Nh = is_token ? HN : HD;
    int K  = is_token ? Nn : Dd;
    int tilesN = Nh / BN;
    int m0 = (blockIdx.x / tilesN) * BM;
    int n0 = (blockIdx.x % tilesN) * BN;

    const __half *A, *B;
    if (is_token) {
        A = g_xt  + (size_t)b  * Dd * Nn + (size_t)m0 * Nn;
        B = g_w1t + (size_t)el * HN * Nn + (size_t)n0 * Nn;
    } else {
        A = g_xc  + (size_t)b  * Nn * Dd + (size_t)m0 * Dd;
        B = g_w1c + (size_t)el * HD * Dd + (size_t)n0 * Dd;
    }

    uint32_t sb = s2u(smem);
    int tid = threadIdx.x, wid = tid >> 5, lane = tid & 31;
    int wm = wid >> 2, wn = wid & 3;

    float acc[4][4][4] = {};
    gemm_pipeline(sb, A, B, K, acc, wm, wn, lane, tid);

    __half* H = g_hid + (size_t)slot * SLOT_STRIDE;
    const float* b1e = (is_token ? tok_b1 : ch_b1) + el * Nh;
    #pragma unroll
    for (int mf = 0; mf < 4; mf++) {
        int m = m0 + wm * 64 + mf * 16 + (lane >> 2);
        #pragma unroll
        for (int nf = 0; nf < 4; nf++) {
            int col = n0 + wn * 32 + nf * 8 + (lane & 3) * 2;
            float bv0 = b1e[col], bv1 = b1e[col + 1];
            #pragma unroll
            for (int half = 0; half < 2; half++) {
                int mm = m + half * 8;
                float v0 = w * gelu_tanh(acc[mf][nf][half * 2]     + bv0);
                float v1 = w * gelu_tanh(acc[mf][nf][half * 2 + 1] + bv1);
                __half2 hh = __floats2half2_rn(v0, v1);
                stcs_u32(H + (size_t)mm * Nh + col, *reinterpret_cast<uint32_t*>(&hh));
            }
        }
    }
}

// ---------------- launch 5: GEMM2 --------------------------------------------
__global__ void __launch_bounds__(256, 2) gemm2_mma(const float* __restrict__ tok_b2,
                                                    const float* __restrict__ ch_b2,
                                                    float* __restrict__ out) {
    extern __shared__ char smem[];
    int b = Bq - 1 - blockIdx.z;
    int n0 = (blockIdx.x / (Dd / BN)) * BM;
    int d0 = (blockIdx.x % (Dd / BN)) * BN;

    int ae[2]; float aw[2]; int cnt = 0;
    #pragma unroll
    for (int e = 0; e < Ee; e++) {
        float wv = g_combine[b * Ee + e];
        if (wv != 0.f && cnt < 2) { ae[cnt] = e; aw[cnt] = wv; cnt++; }
    }

    uint32_t sb = s2u(smem);
    int tid = threadIdx.x, wid = tid >> 5, lane = tid & 31;
    int wm = wid >> 2, wn = wid & 3;

    float acc[4][4][4] = {};
    for (int xi = 0; xi < cnt; xi++) {
        int e = ae[xi];
        int slot = g_slot[b * Ee + e];
        const __half *A, *B;
        int K;
        if (e < E_TOK) {
            A = g_w2t + (size_t)e * Nn * HN + (size_t)n0 * HN;
            B = g_hid + (size_t)slot * SLOT_STRIDE + (size_t)d0 * HN;
            K = HN;
        } else {
            A = g_hid + (size_t)slot * SLOT_STRIDE + (size_t)n0 * HD;
            B = g_w2c + (size_t)(e - E_TOK) * Dd * HD + (size_t)d0 * HD;
            K = HD;
        }
        gemm_pipeline(sb, A, B, K, acc, wm, wn, lane, tid);
    }

    #pragma unroll
    for (int mf = 0; mf < 4; mf++) {
        int m = n0 + wm * 64 + mf * 16 + (lane >> 2);
        #pragma unroll
        for (int half = 0; half < 2; half++) {
            int mm = m + half * 8;
            float rowb = 0.f;
            #pragma unroll
            for (int xi = 0; xi < 2; xi++)
                if (xi < cnt && ae[xi] < E_TOK) rowb += aw[xi] * tok_b2[ae[xi] * Nn + mm];
            float* orow = out + ((size_t)b * Nn + mm) * Dd;
            #pragma unroll
            for (int nf = 0; nf < 4; nf++) {
                int col = d0 + wn * 32 + nf * 8 + (lane & 3) * 2;
                float cb0 = 0.f, cb1 = 0.f;
                #pragma unroll
                for (int xi = 0; xi < 2; xi++)
                    if (xi < cnt && ae[xi] >= E_TOK) {
                        const float* cb = ch_b2 + (ae[xi] - E_TOK) * Dd;
                        cb0 += aw[xi] * cb[col];
                        cb1 += aw[xi] * cb[col + 1];
                    }
                stcs_v2f32(orow + col,
                           acc[mf][nf][half * 2]     + rowb + cb0,
                           acc[mf][nf][half * 2 + 1] + rowb + cb1);
            }
        }
    }
}

// ---------------- launch -----------------------------------------------------
extern "C" void kernel_launch(void* const* d_in, const int* in_sizes, int n_in,
                              void* d_out, int out_size) {
    const float* x      = (const float*)d_in[0];
    const float* rw     = (const float*)d_in[1];
    const float* tok_w1 = (const float*)d_in[2];
    const float* tok_b1 = (const float*)d_in[3];
    const float* tok_w2 = (const float*)d_in[4];
    const float* tok_b2 = (const float*)d_in[5];
    const float* ch_w1  = (const float*)d_in[6];
    const float* ch_b1  = (const float*)d_in[7];
    const float* ch_w2  = (const float*)d_in[8];
    const float* ch_b2  = (const float*)d_in[9];
    float* out = (float*)d_out;
    (void)in_sizes; (void)n_in;
    float* auxp = (out_size > Bq * Nn * Dd) ? (out + (size_t)Bq * Nn * Dd) : nullptr;

    cudaFuncSetAttribute(gemm1_mma, cudaFuncAttributeMaxDynamicSharedMemorySize, SMEM_DYN);
    cudaFuncSetAttribute(gemm2_mma, cudaFuncAttributeMaxDynamicSharedMemorySize, SMEM_DYN);

    // launch 1: x conversion + mean partials (fused)
    xcvt_mean_kernel<<<dim3(Dd / 32, Nn / 32, Bq), dim3(32, 8)>>>(x);

    // launch 2: mean reduce + gate + work list (fused, single block)
    gate_kernel<<<1, 256>>>(rw, auxp);

    // launch 3: all weight conversions
    {
        __half *p_w1t, *p_w2t, *p_w1c, *p_w2c;
        cudaGetSymbolAddress((void**)&p_w1t, g_w1t);
        cudaGetSymbolAddress((void**)&p_w2t, g_w2t);
        cudaGetSymbolAddress((void**)&p_w1c, g_w1c);
        cudaGetSymbolAddress((void**)&p_w2c, g_w2c);
        int n4 = 2 * (N4_TW + N4_CW);
        cvt_all_kernel<<<(n4 + 255) / 256, 256>>>(tok_w1, tok_w2, ch_w1, ch_w2,
                                                  p_w1t, p_w2t, p_w1c, p_w2c);
    }

    // launch 4 (ncu -s 5 -c 1 captures this one): GEMM1
    dim3 g1(192, Bq * 2);
    gemm1_mma<<<g1, 256, SMEM_DYN>>>(tok_b1, ch_b1);

    // launch 5: GEMM2
    dim3 g2((Nn / BM) * (Dd / BN), 1, Bq);
    gemm2_mma<<<g2, 256, SMEM_DYN>>>(tok_b2, ch_b2, out);
}

// round 10
// speedup vs baseline: 1.0435x; 1.0435x over previous
#include <cuda_runtime.h>
#include <cuda_fp16.h>
#include <math.h>
#include <stdint.h>

#define Bq    32
#define Nn    1024
#define Dd    768
#define E_TOK 4
#define E_CH  4
#define Ee    8
#define HN    4096
#define HD    3072

#define SLOT_STRIDE 3145728   // 768*4096 == 1024*3072

// ---------------- scratch (__device__ globals: sanctioned scratch path) -----
__device__ float g_pmean[Bq * 32 * Dd];   // per-(b, n-chunk32) partial column sums
__device__ float g_xmean[Bq * Dd];
__device__ float g_combine[Bq * Ee];
__device__ int   g_slot[Bq * Ee];
__device__ int   g_wl[Bq * 2];            // compact work list: (b<<8)|eg

__device__ __half g_xt [(size_t)Bq * Dd * Nn];
__device__ __half g_xc [(size_t)Bq * Nn * Dd];
__device__ __half g_w1t[(size_t)E_TOK * HN * Nn];
__device__ __half g_w2t[(size_t)E_TOK * Nn * HN];
__device__ __half g_w1c[(size_t)E_CH * HD * Dd];
__device__ __half g_w2c[(size_t)E_CH * Dd * HD];
__device__ __half g_hid[(size_t)Bq * 2 * SLOT_STRIDE];

// ---------------- smem geometry ---------------------------------------------
#define BM 128
#define BN 128
#define BK 64
#define SKB 144
#define A_BYTES (BM * SKB)
#define B_BYTES (BN * SKB)
#define ST_BYTES (A_BYTES + B_BYTES)   // 36864
#define NSTAGE 3
#define SMEM_DYN (NSTAGE * ST_BYTES)   // 110592 -> 2 CTA/SM

// ---------------- PTX helpers ------------------------------------------------
__device__ __forceinline__ uint32_t s2u(const void* p) {
    uint32_t a;
    asm("{ .reg .u64 t; cvta.to.shared.u64 t, %1; cvt.u32.u64 %0, t; }" : "=r"(a) : "l"(p));
    return a;
}
__device__ __forceinline__ void cp16(uint32_t sdst, const void* g) {
    asm volatile("cp.async.cg.shared.global [%0], [%1], 16;" :: "r"(sdst), "l"(g));
}
__device__ __forceinline__ void cp_commit() { asm volatile("cp.async.commit_group;" ::: "memory"); }
__device__ __forceinline__ void cp_wait1() { asm volatile("cp.async.wait_group 1;" ::: "memory"); }
__device__ __forceinline__ void cp_wait0() { asm volatile("cp.async.wait_group 0;" ::: "memory"); }
__device__ __forceinline__ void ldsm4(uint32_t* r, uint32_t addr) {
    asm volatile("ldmatrix.sync.aligned.m8n8.x4.shared.b16 {%0,%1,%2,%3}, [%4];"
                 : "=r"(r[0]), "=r"(r[1]), "=r"(r[2]), "=r"(r[3]) : "r"(addr));
}
__device__ __forceinline__ void mma_f16(float* c, const uint32_t* a, const uint32_t* b) {
    asm volatile(
        "mma.sync.aligned.m16n8k16.row.col.f32.f16.f16.f32 "
        "{%0,%1,%2,%3}, {%4,%5,%6,%7}, {%8,%9}, {%0,%1,%2,%3};"
        : "+f"(c[0]), "+f"(c[1]), "+f"(c[2]), "+f"(c[3])
        : "r"(a[0]), "r"(a[1]), "r"(a[2]), "r"(a[3]), "r"(b[0]), "r"(b[1]));
}
__device__ __forceinline__ void stcs_u16(__half* p, __half v) {
    unsigned short u = *reinterpret_cast<unsigned short*>(&v);
    asm volatile("st.global.cs.u16 [%0], %1;" :: "l"(p), "h"(u) : "memory");
}
__device__ __forceinline__ void stcs_u32(void* p, uint32_t v) {
    asm volatile("st.global.cs.u32 [%0], %1;" :: "l"(p), "r"(v) : "memory");
}
__device__ __forceinline__ void stcs_v2u32(void* p, uint32_t a, uint32_t b) {
    asm volatile("st.global.cs.v2.u32 [%0], {%1, %2};" :: "l"(p), "r"(a), "r"(b) : "memory");
}
__device__ __forceinline__ void stcs_v2f32(void* p, float a, float b) {
    asm volatile("st.global.cs.v2.f32 [%0], {%1, %2};" :: "l"(p), "f"(a), "f"(b) : "memory");
}
__device__ __forceinline__ float gelu_tanh(float v) {
    float c = 0.7978845608028654f * (v + 0.044715f * v * v * v);
    return 0.5f * v * (1.0f + tanhf(c));
}

// ---------------- GEMM core --------------------------------------------------
template <int R>
__device__ __forceinline__ void cpa_tile(uint32_t sdst, const __half* __restrict__ g,
                                         int k0, int strideK, int tid) {
    #pragma unroll
    for (int i = 0; i < R * 8 / 256; i++) {
        int c = tid + i * 256;
        int row = c >> 3, seg = c & 7;
        cp16(sdst + row * SKB + seg * 16,
             g + (size_t)row * strideK + k0 + seg * 8);
    }
}

__device__ __forceinline__ void issue_stage(uint32_t sbase,
                                            const __half* A, const __half* B,
                                            int k0, int strideK, int tid) {
    cpa_tile<BM>(sbase, A, k0, strideK, tid);
    cpa_tile<BN>(sbase + A_BYTES, B, k0, strideK, tid);
    cp_commit();
}

__device__ __forceinline__ void compute_stage(uint32_t s, float acc[4][4][4],
                                              int wm, int wn, int lane) {
    uint32_t aRow = lane & 15;
    uint32_t aK   = (lane >> 4) * 8;
    uint32_t bRow = (lane & 7) + ((lane >> 4) & 1) * 8;
    uint32_t bK   = ((lane >> 3) & 1) * 8;
    uint32_t sA = s, sB = s + A_BYTES;
    #pragma unroll
    for (int ks = 0; ks < 4; ks++) {
        uint32_t b[4][2];
        #pragma unroll
        for (int q = 0; q < 2; q++) {
            uint32_t t[4];
            ldsm4(t, sB + (wn * 32 + q * 16 + bRow) * SKB + (ks * 16 + bK) * 2);
            b[q * 2][0] = t[0]; b[q * 2][1] = t[1];
            b[q * 2 + 1][0] = t[2]; b[q * 2 + 1][1] = t[3];
        }
        #pragma unroll
        for (int mf = 0; mf < 4; mf++) {
            uint32_t a[4];
            ldsm4(a, sA + (wm * 64 + mf * 16 + aRow) * SKB + (ks * 16 + aK) * 2);
            #pragma unroll
            for (int nf = 0; nf < 4; nf++)
                mma_f16(acc[mf][nf], a, b[nf]);
        }
    }
}

// issue-before-compute: during compute(c), groups c+1 AND c+2 are in flight.
// Buffer safety: issue(c+2) writes buf (c+2)%3 == (c-1)%3, whose compute
// finished before this iteration's __syncthreads.
__device__ __forceinline__ void gemm_pipeline(uint32_t sb,
                                              const __half* A, const __half* B, int K,
                                              float acc[4][4][4],
                                              int wm, int wn, int lane, int tid) {
    int nch = K / BK;
    issue_stage(sb,            A, B, 0,  K, tid);
    issue_stage(sb + ST_BYTES, A, B, BK, K, tid);
    for (int c = 0; c < nch; c++) {
        if (c + 1 < nch) cp_wait1(); else cp_wait0();
        __syncthreads();
        if (c + 2 < nch)
            issue_stage(sb + ((c + 2) % 3) * ST_BYTES, A, B, (c + 2) * BK, K, tid);
        compute_stage(sb + (c % 3) * ST_BYTES, acc, wm, wn, lane);
    }
    __syncthreads();
}

// ---------------- launch 1: fused x conversion + mean partials ---------------
__global__ void xcvt_mean_kernel(const float* __restrict__ x) {
    __shared__ float t[32][33];
    __shared__ float ps[8][32];
    int b = blockIdx.z;
    int d0 = blockIdx.x * 32, n0 = blockIdx.y * 32;
    int tx = threadIdx.x, ty = threadIdx.y;
    const float* xb = x + (size_t)b * Nn * Dd;
    size_t cbase = (size_t)b * Nn * Dd;
    float part = 0.f;
    #pragma unroll
    for (int k = 0; k < 32; k += 8) {
        float v = xb[(size_t)(n0 + ty + k) * Dd + d0 + tx];
        t[ty + k][tx] = v;
        part += v;
        stcs_u16(g_xc + cbase + (size_t)(n0 + ty + k) * Dd + d0 + tx, __float2half_rn(v));
    }
    ps[ty][tx] = part;
    __syncthreads();
    size_t base = (size_t)b * Dd * Nn;
    #pragma unroll
    for (int k = 0; k < 32; k += 8)
        stcs_u16(g_xt + base + (size_t)(d0 + ty + k) * Nn + n0 + tx,
                 __float2half_rn(t[tx][ty + k]));
    if (ty == 0) {
        float s = 0.f;
        #pragma unroll
        for (int j = 0; j < 8; j++) s += ps[j][tx];
        g_pmean[((size_t)b * 32 + blockIdx.y) * Dd + d0 + tx] = s;
    }
}

// ---------------- launch 2: weight conversions + parallel mean reduce --------
#define N4_TW (E_TOK * HN * Nn / 4)
#define N4_CW (E_CH * HD * Dd / 4)
__global__ void cvt_mean_kernel(const float* __restrict__ tok_w1, const float* __restrict__ tok_w2,
                                const float* __restrict__ ch_w1,  const float* __restrict__ ch_w2,
                                __half* __restrict__ o1, __half* __restrict__ o2,
                                __half* __restrict__ o3, __half* __restrict__ o4) {
    if (blockIdx.x < Bq) {
        // parallel mean reduce (fixed order -> deterministic)
        int b = blockIdx.x;
        for (int d = threadIdx.x; d < Dd; d += blockDim.x) {
            float s = 0.f;
            #pragma unroll 8
            for (int c = 0; c < 32; c++) s += g_pmean[((size_t)b * 32 + c) * Dd + d];
            g_xmean[b * Dd + d] = s * (1.0f / Nn);
        }
        return;
    }
    int i = (blockIdx.x - Bq) * blockDim.x + threadIdx.x;
    const float* in; __half* out; int idx;
    if (i < N4_TW)                    { in = tok_w1; out = o1; idx = i; }
    else if (i < 2 * N4_TW)           { in = tok_w2; out = o2; idx = i - N4_TW; }
    else if (i < 2 * N4_TW + N4_CW)   { in = ch_w1;  out = o3; idx = i - 2 * N4_TW; }
    else if (i < 2 * (N4_TW + N4_CW)) { in = ch_w2;  out = o4; idx = i - 2 * N4_TW - N4_CW; }
    else return;
    float4 v = ((const float4*)in)[idx];
    __half2 h0 = __floats2half2_rn(v.x, v.y);
    __half2 h1 = __floats2half2_rn(v.z, v.w);
    stcs_v2u32((char*)out + 8 * (size_t)idx,
               *reinterpret_cast<uint32_t*>(&h0), *reinterpret_cast<uint32_t*>(&h1));
}

// ---------------- launch 3: gate + work list ---------------------------------
__global__ void gate_kernel(const float* __restrict__ rw, float* __restrict__ aux_out) {
    __shared__ float s_probs[Bq][Ee];
    __shared__ int   s_top1[Bq];
    __shared__ int   s_top2[Bq];
    int warp = threadIdx.x >> 5, lane = threadIdx.x & 31;
    int nwarp = blockDim.x >> 5;
    for (int b = warp; b < Bq; b += nwarp) {
        float logits[Ee];
        #pragma unroll
        for (int e = 0; e < Ee; e++) {
            float s = 0.f;
            for (int d = lane; d < Dd; d += 32)
                s += g_xmean[b * Dd + d] * rw[e * Dd + d];
            #pragma unroll
            for (int o = 16; o; o >>= 1) s += __shfl_xor_sync(0xffffffffu, s, o);
            logits[e] = s;
        }
        if (lane == 0) {
            float mx = logits[0];
            #pragma unroll
            for (int e = 1; e < Ee; e++) mx = fmaxf(mx, logits[e]);
            float p[Ee], se = 0.f;
            #pragma unroll
            for (int e = 0; e < Ee; e++) { p[e] = expf(logits[e] - mx); se += p[e]; }
            float inv = 1.0f / se;
            #pragma unroll
            for (int e = 0; e < Ee; e++) p[e] *= inv;
            int i0 = 0;
            #pragma unroll
            for (int e = 1; e < Ee; e++) if (p[e] > p[i0]) i0 = e;
            int i1 = (i0 == 0) ? 1 : 0;
            #pragma unroll
            for (int e = 0; e < Ee; e++) if (e != i1 && e != i0 && p[e] > p[i1]) i1 = e;
            float ws = p[i0] + p[i1];
            #pragma unroll
            for (int e = 0; e < Ee; e++) { g_combine[b * Ee + e] = 0.f; g_slot[b * Ee + e] = -1; }
            g_combine[b * Ee + i0] = p[i0] / ws;  g_slot[b * Ee + i0] = b * 2;
            g_combine[b * Ee + i1] = p[i1] / ws;  g_slot[b * Ee + i1] = b * 2 + 1;
            #pragma unroll
            for (int e = 0; e < Ee; e++) s_probs[b][e] = p[e];
            s_top1[b] = i0;
            s_top2[b] = i1;
        }
    }
    __syncthreads();
    if (threadIdx.x == 0) {
        int cnt = 0;
        for (int b = 0; b < Bq; b++)
            for (int e = 0; e < Ee; e++)
                if (e == s_top1[b] || e == s_top2[b]) g_wl[cnt++] = (b << 8) | e;
        if (aux_out != nullptr) {
            float aux = 0.f;
            for (int e = 0; e < Ee; e++) {
                float pm = 0.f; int c = 0;
                for (int b = 0; b < Bq; b++) { pm += s_probs[b][e]; c += (s_top1[b] == e); }
                aux += (pm / Bq) * ((float)c / Bq);
            }
            aux_out[0] = (float)Ee * aux;
        }
    }
}

// ---------------- launch 4 (ncu-captured): GEMM1 -----------------------------
__global__ void __launch_bounds__(256, 2) gemm1_mma(const float* __restrict__ tok_b1,
                                                    const float* __restrict__ ch_b1) {
    extern __shared__ char smem[];
    int code = g_wl[blockIdx.y];
    int b = code >> 8, eg = code & 255;
    int is_token = (eg < E_TOK);
    int el = is_token ? eg : (eg - E_TOK);
    float w = g_combine[b * Ee + eg];
    int slot = g_slot[b * Ee + eg];
    int Nh = is_token ? HN : HD;
    int K  = is_token ? Nn : Dd;
    int tilesN = Nh / BN;
    int m0 = (blockIdx.x / tilesN) * BM;
    int n0 = (blockIdx.x % tilesN) * BN;

    const __half *A, *B;
    if (is_token) {
        A = g_xt  + (size_t)b  * Dd * Nn + (size_t)m0 * Nn;
        B = g_w1t + (size_t)el * HN * Nn + (size_t)n0 * Nn;
    } else {
        A = g_xc  + (size_t)b  * Nn * Dd + (size_t)m0 * Dd;
        B = g_w1c + (size_t)el * HD * Dd + (size_t)n0 * Dd;
    }

    uint32_t sb = s2u(smem);
    int tid = threadIdx.x, wid = tid >> 5, lane = tid & 31;
    int wm = wid >> 2, wn = wid & 3;

    float acc[4][4][4] = {};
    gemm_pipeline(sb, A, B, K, acc, wm, wn, lane, tid);

    __half* H = g_hid + (size_t)slot * SLOT_STRIDE;
    const float* b1e = (is_token ? tok_b1 : ch_b1) + el * Nh;
    #pragma unroll
    for (int mf = 0; mf < 4; mf++) {
        int m = m0 + wm * 64 + mf * 16 + (lane >> 2);
        #pragma unroll
        for (int nf = 0; nf < 4; nf++) {
            int col = n0 + wn * 32 + nf * 8 + (lane & 3) * 2;
            float bv0 = b1e[col], bv1 = b1e[col + 1];
            #pragma unroll
            for (int half = 0; half < 2; half++) {
                int mm = m + half * 8;
                float v0 = w * gelu_tanh(acc[mf][nf][half * 2]     + bv0);
                float v1 = w * gelu_tanh(acc[mf][nf][half * 2 + 1] + bv1);
                __half2 hh = __floats2half2_rn(v0, v1);
                stcs_u32(H + (size_t)mm * Nh + col, *reinterpret_cast<uint32_t*>(&hh));
            }
        }
    }
}

// ---------------- launch 5: GEMM2 --------------------------------------------
__global__ void __launch_bounds__(256, 2) gemm2_mma(const float* __restrict__ tok_b2,
                                                    const float* __restrict__ ch_b2,
                                                    float* __restrict__ out) {
    extern __shared__ char smem[];
    int b = Bq - 1 - blockIdx.z;   // reversed: catch gemm1's freshest hid in L2
    int n0 = (blockIdx.x / (Dd / BN)) * BM;
    int d0 = (blockIdx.x % (Dd / BN)) * BN;

    int ae[2]; float aw[2]; int cnt = 0;
    #pragma unroll
    for (int e = 0; e < Ee; e++) {
        float wv = g_combine[b * Ee + e];
        if (wv != 0.f && cnt < 2) { ae[cnt] = e; aw[cnt] = wv; cnt++; }
    }

    uint32_t sb = s2u(smem);
    int tid = threadIdx.x, wid = tid >> 5, lane = tid & 31;
    int wm = wid >> 2, wn = wid & 3;

    float acc[4][4][4] = {};
    for (int xi = 0; xi < cnt; xi++) {
        int e = ae[xi];
        int slot = g_slot[b * Ee + e];
        const __half *A, *B;
        int K;
        if (e < E_TOK) {
            A = g_w2t + (size_t)e * Nn * HN + (size_t)n0 * HN;
            B = g_hid + (size_t)slot * SLOT_STRIDE + (size_t)d0 * HN;
            K = HN;
        } else {
            A = g_hid + (size_t)slot * SLOT_STRIDE + (size_t)n0 * HD;
            B = g_w2c + (size_t)(e - E_TOK) * Dd * HD + (size_t)d0 * HD;
            K = HD;
        }
        gemm_pipeline(sb, A, B, K, acc, wm, wn, lane, tid);
    }

    #pragma unroll
    for (int mf = 0; mf < 4; mf++) {
        int m = n0 + wm * 64 + mf * 16 + (lane >> 2);
        #pragma unroll
        for (int half = 0; half < 2; half++) {
            int mm = m + half * 8;
            float rowb = 0.f;
            #pragma unroll
            for (int xi = 0; xi < 2; xi++)
                if (xi < cnt && ae[xi] < E_TOK) rowb += aw[xi] * tok_b2[ae[xi] * Nn + mm];
            float* orow = out + ((size_t)b * Nn + mm) * Dd;
            #pragma unroll
            for (int nf = 0; nf < 4; nf++) {
                int col = d0 + wn * 32 + nf * 8 + (lane & 3) * 2;
                float cb0 = 0.f, cb1 = 0.f;
                #pragma unroll
                for (int xi = 0; xi < 2; xi++)
                    if (xi < cnt && ae[xi] >= E_TOK) {
                        const float* cb = ch_b2 + (ae[xi] - E_TOK) * Dd;
                        cb0 += aw[xi] * cb[col];
                        cb1 += aw[xi] * cb[col + 1];
                    }
                stcs_v2f32(orow + col,
                           acc[mf][nf][half * 2]     + rowb + cb0,
                           acc[mf][nf][half * 2 + 1] + rowb + cb1);
            }
        }
    }
}

// ---------------- launch -----------------------------------------------------
extern "C" void kernel_launch(void* const* d_in, const int* in_sizes, int n_in,
                              void* d_out, int out_size) {
    const float* x      = (const float*)d_in[0];
    const float* rw     = (const float*)d_in[1];
    const float* tok_w1 = (const float*)d_in[2];
    const float* tok_b1 = (const float*)d_in[3];
    const float* tok_w2 = (const float*)d_in[4];
    const float* tok_b2 = (const float*)d_in[5];
    const float* ch_w1  = (const float*)d_in[6];
    const float* ch_b1  = (const float*)d_in[7];
    const float* ch_w2  = (const float*)d_in[8];
    const float* ch_b2  = (const float*)d_in[9];
    float* out = (float*)d_out;
    (void)in_sizes; (void)n_in;
    float* auxp = (out_size > Bq * Nn * Dd) ? (out + (size_t)Bq * Nn * Dd) : nullptr;

    cudaFuncSetAttribute(gemm1_mma, cudaFuncAttributeMaxDynamicSharedMemorySize, SMEM_DYN);
    cudaFuncSetAttribute(gemm2_mma, cudaFuncAttributeMaxDynamicSharedMemorySize, SMEM_DYN);

    // launch 1: x conversion + mean partials (fused)
    xcvt_mean_kernel<<<dim3(Dd / 32, Nn / 32, Bq), dim3(32, 8)>>>(x);

    // launch 2: weight conversions + parallel mean reduce (blocks 0..31)
    {
        __half *p_w1t, *p_w2t, *p_w1c, *p_w2c;
        cudaGetSymbolAddress((void**)&p_w1t, g_w1t);
        cudaGetSymbolAddress((void**)&p_w2t, g_w2t);
        cudaGetSymbolAddress((void**)&p_w1c, g_w1c);
        cudaGetSymbolAddress((void**)&p_w2c, g_w2c);
        int n4 = 2 * (N4_TW + N4_CW);
        cvt_mean_kernel<<<Bq + (n4 + 255) / 256, 256>>>(tok_w1, tok_w2, ch_w1, ch_w2,
                                                        p_w1t, p_w2t, p_w1c, p_w2c);
    }

    // launch 3: gate + work list
    gate_kernel<<<1, 256>>>(rw, auxp);

    // launch 4 (ncu captures this one): GEMM1
    dim3 g1(192, Bq * 2);
    gemm1_mma<<<g1, 256, SMEM_DYN>>>(tok_b1, ch_b1);

    // launch 5: GEMM2
    dim3 g2((Nn / BM) * (Dd / BN), 1, Bq);
    gemm2_mma<<<g2, 256, SMEM_DYN>>>(tok_b2, ch_b2, out);
}

// round 12
// speedup vs baseline: 1.1164x; 1.0699x over previous
#include <cuda_runtime.h>
#include <cuda_fp16.h>
#include <math.h>
#include <stdint.h>

#define Bq    32
#define Nn    1024
#define Dd    768
#define E_TOK 4
#define E_CH  4
#define Ee    8
#define HN    4096
#define HD    3072

#define SLOT_STRIDE 3145728   // 768*4096 == 1024*3072

// ---------------- scratch (__device__ globals: sanctioned scratch path) -----
__device__ float g_pmean[Bq * 32 * Dd];   // per-(b, n-chunk32) partial column sums
__device__ float g_xmean[Bq * Dd];
__device__ float g_combine[Bq * Ee];
__device__ int   g_slot[Bq * Ee];
__device__ int   g_wl[Bq * 2];            // compact work list: (b<<8)|eg

__device__ __half g_xt [(size_t)Bq * Dd * Nn];
__device__ __half g_xc [(size_t)Bq * Nn * Dd];
__device__ __half g_w1t[(size_t)E_TOK * HN * Nn];
__device__ __half g_w2t[(size_t)E_TOK * Nn * HN];
__device__ __half g_w1c[(size_t)E_CH * HD * Dd];
__device__ __half g_w2c[(size_t)E_CH * Dd * HD];
__device__ __half g_hid[(size_t)Bq * 2 * SLOT_STRIDE];

// ---------------- smem geometry ---------------------------------------------
#define BM 128
#define BN 128
#define BK 64
#define SKB 144
#define A_BYTES (BM * SKB)
#define B_BYTES (BN * SKB)
#define ST_BYTES (A_BYTES + B_BYTES)   // 36864
#define NSTAGE 3
#define SMEM_DYN (NSTAGE * ST_BYTES)   // 110592 -> 2 CTA/SM

// ---------------- PTX helpers ------------------------------------------------
__device__ __forceinline__ uint32_t s2u(const void* p) {
    uint32_t a;
    asm("{ .reg .u64 t; cvta.to.shared.u64 t, %1; cvt.u32.u64 %0, t; }" : "=r"(a) : "l"(p));
    return a;
}
__device__ __forceinline__ void cp16(uint32_t sdst, const void* g) {
    asm volatile("cp.async.cg.shared.global [%0], [%1], 16;" :: "r"(sdst), "l"(g));
}
__device__ __forceinline__ void cp_commit() { asm volatile("cp.async.commit_group;" ::: "memory"); }
__device__ __forceinline__ void cp_wait1() { asm volatile("cp.async.wait_group 1;" ::: "memory"); }
__device__ __forceinline__ void cp_wait0() { asm volatile("cp.async.wait_group 0;" ::: "memory"); }
__device__ __forceinline__ void ldsm4(uint32_t* r, uint32_t addr) {
    asm volatile("ldmatrix.sync.aligned.m8n8.x4.shared.b16 {%0,%1,%2,%3}, [%4];"
                 : "=r"(r[0]), "=r"(r[1]), "=r"(r[2]), "=r"(r[3]) : "r"(addr));
}
__device__ __forceinline__ void mma_f16(float* c, const uint32_t* a, const uint32_t* b) {
    asm volatile(
        "mma.sync.aligned.m16n8k16.row.col.f32.f16.f16.f32 "
        "{%0,%1,%2,%3}, {%4,%5,%6,%7}, {%8,%9}, {%0,%1,%2,%3};"
        : "+f"(c[0]), "+f"(c[1]), "+f"(c[2]), "+f"(c[3])
        : "r"(a[0]), "r"(a[1]), "r"(a[2]), "r"(a[3]), "r"(b[0]), "r"(b[1]));
}
__device__ __forceinline__ void stcs_u16(__half* p, __half v) {
    unsigned short u = *reinterpret_cast<unsigned short*>(&v);
    asm volatile("st.global.cs.u16 [%0], %1;" :: "l"(p), "h"(u) : "memory");
}
__device__ __forceinline__ void stcs_u32(void* p, uint32_t v) {
    asm volatile("st.global.cs.u32 [%0], %1;" :: "l"(p), "r"(v) : "memory");
}
__device__ __forceinline__ void stcs_v2u32(void* p, uint32_t a, uint32_t b) {
    asm volatile("st.global.cs.v2.u32 [%0], {%1, %2};" :: "l"(p), "r"(a), "r"(b) : "memory");
}
__device__ __forceinline__ void stcs_v2f32(void* p, float a, float b) {
    asm volatile("st.global.cs.v2.f32 [%0], {%1, %2};" :: "l"(p), "f"(a), "f"(b) : "memory");
}
__device__ __forceinline__ float gelu_tanh(float v) {
    float c = 0.7978845608028654f * (v + 0.044715f * v * v * v);
    return 0.5f * v * (1.0f + tanhf(c));
}

// ---------------- GEMM core --------------------------------------------------
template <int R>
__device__ __forceinline__ void cpa_tile(uint32_t sdst, const __half* __restrict__ g,
                                         int k0, int strideK, int tid) {
    #pragma unroll
    for (int i = 0; i < R * 8 / 256; i++) {
        int c = tid + i * 256;
        int row = c >> 3, seg = c & 7;
        cp16(sdst + row * SKB + seg * 16,
             g + (size_t)row * strideK + k0 + seg * 8);
    }
}

__device__ __forceinline__ void issue_stage(uint32_t sbase,
                                            const __half* A, const __half* B,
                                            int k0, int strideK, int tid) {
    cpa_tile<BM>(sbase, A, k0, strideK, tid);
    cpa_tile<BN>(sbase + A_BYTES, B, k0, strideK, tid);
    cp_commit();
}

// Software-pipelined: B-frags of ks+1 and A-frag of mf+1 are prefetched while
// the current 16 HMMAs drain — LDSM latency hides under tensor work.
__device__ __forceinline__ void compute_stage(uint32_t s, float acc[4][4][4],
                                              int wm, int wn, int lane) {
    uint32_t aRow = lane & 15;
    uint32_t aK   = (lane >> 4) * 8;
    uint32_t bRow = (lane & 7) + ((lane >> 4) & 1) * 8;
    uint32_t bK   = ((lane >> 3) & 1) * 8;
    uint32_t sA = s, sB = s + A_BYTES;

    uint32_t b[2][4][2];   // [parity][nf][frag]
    uint32_t a[2][4];      // [parity][frag]

    // preload ks=0 B-frags and mf=0 A-frag
    #pragma unroll
    for (int q = 0; q < 2; q++) {
        uint32_t t[4];
        ldsm4(t, sB + (wn * 32 + q * 16 + bRow) * SKB + bK * 2);
        b[0][q * 2][0] = t[0]; b[0][q * 2][1] = t[1];
        b[0][q * 2 + 1][0] = t[2]; b[0][q * 2 + 1][1] = t[3];
    }
    ldsm4(a[0], sA + (wm * 64 + aRow) * SKB + aK * 2);

    #pragma unroll
    for (int ks = 0; ks < 4; ks++) {
        int kp = ks & 1;
        // prefetch next ks's B-frags
        if (ks < 3) {
            #pragma unroll
            for (int q = 0; q < 2; q++) {
                uint32_t t[4];
                ldsm4(t, sB + (wn * 32 + q * 16 + bRow) * SKB + ((ks + 1) * 16 + bK) * 2);
                b[kp ^ 1][q * 2][0] = t[0]; b[kp ^ 1][q * 2][1] = t[1];
                b[kp ^ 1][q * 2 + 1][0] = t[2]; b[kp ^ 1][q * 2 + 1][1] = t[3];
            }
        }
        #pragma unroll
        for (int mf = 0; mf < 4; mf++) {
            int mp = mf & 1;
            // prefetch next A-frag (next mf, or mf=0 of next ks)
            if (mf < 3) {
                ldsm4(a[mp ^ 1], sA + (wm * 64 + (mf + 1) * 16 + aRow) * SKB + (ks * 16 + aK) * 2);
            } else if (ks < 3) {
                ldsm4(a[mp ^ 1], sA + (wm * 64 + aRow) * SKB + ((ks + 1) * 16 + aK) * 2);
            }
            #pragma unroll
            for (int nf = 0; nf < 4; nf++)
                mma_f16(acc[mf][nf], a[mp], b[kp][nf]);
        }
    }
}

// validated R7 order: compute first, then prefetch c+2
__device__ __forceinline__ void gemm_pipeline(uint32_t sb,
                                              const __half* A, const __half* B, int K,
                                              float acc[4][4][4],
                                              int wm, int wn, int lane, int tid) {
    int nch = K / BK;
    issue_stage(sb,            A, B, 0,  K, tid);
    issue_stage(sb + ST_BYTES, A, B, BK, K, tid);
    for (int c = 0; c < nch; c++) {
        if (c + 1 < nch) cp_wait1(); else cp_wait0();
        __syncthreads();
        compute_stage(sb + (c % 3) * ST_BYTES, acc, wm, wn, lane);
        if (c + 2 < nch)
            issue_stage(sb + ((c + 2) % 3) * ST_BYTES, A, B, (c + 2) * BK, K, tid);
    }
    __syncthreads();
}

// ---------------- launch 1: fused x conversion + mean partials ---------------
__global__ void xcvt_mean_kernel(const float* __restrict__ x) {
    __shared__ float t[32][33];
    __shared__ float ps[8][32];
    int b = blockIdx.z;
    int d0 = blockIdx.x * 32, n0 = blockIdx.y * 32;
    int tx = threadIdx.x, ty = threadIdx.y;
    const float* xb = x + (size_t)b * Nn * Dd;
    size_t cbase = (size_t)b * Nn * Dd;
    float part = 0.f;
    #pragma unroll
    for (int k = 0; k < 32; k += 8) {
        float v = xb[(size_t)(n0 + ty + k) * Dd + d0 + tx];
        t[ty + k][tx] = v;
        part += v;
        stcs_u16(g_xc + cbase + (size_t)(n0 + ty + k) * Dd + d0 + tx, __float2half_rn(v));
    }
    ps[ty][tx] = part;
    __syncthreads();
    size_t base = (size_t)b * Dd * Nn;
    #pragma unroll
    for (int k = 0; k < 32; k += 8)
        stcs_u16(g_xt + base + (size_t)(d0 + ty + k) * Nn + n0 + tx,
                 __float2half_rn(t[tx][ty + k]));
    if (ty == 0) {
        float s = 0.f;
        #pragma unroll
        for (int j = 0; j < 8; j++) s += ps[j][tx];
        g_pmean[((size_t)b * 32 + blockIdx.y) * Dd + d0 + tx] = s;
    }
}

// ---------------- launch 2: weight conversions + parallel mean reduce --------
#define N4_TW (E_TOK * HN * Nn / 4)
#define N4_CW (E_CH * HD * Dd / 4)
__global__ void cvt_mean_kernel(const float* __restrict__ tok_w1, const float* __restrict__ tok_w2,
                                const float* __restrict__ ch_w1,  const float* __restrict__ ch_w2,
                                __half* __restrict__ o1, __half* __restrict__ o2,
                                __half* __restrict__ o3, __half* __restrict__ o4) {
    if (blockIdx.x < Bq) {
        int b = blockIdx.x;
        for (int d = threadIdx.x; d < Dd; d += blockDim.x) {
            float s = 0.f;
            #pragma unroll 8
            for (int c = 0; c < 32; c++) s += g_pmean[((size_t)b * 32 + c) * Dd + d];
            g_xmean[b * Dd + d] = s * (1.0f / Nn);
        }
        return;
    }
    int i = (blockIdx.x - Bq) * blockDim.x + threadIdx.x;
    const float* in; __half* out; int idx;
    if (i < N4_TW)                    { in = tok_w1; out = o1; idx = i; }
    else if (i < 2 * N4_TW)           { in = tok_w2; out = o2; idx = i - N4_TW; }
    else if (i < 2 * N4_TW + N4_CW)   { in = ch_w1;  out = o3; idx = i - 2 * N4_TW; }
    else if (i < 2 * (N4_TW + N4_CW)) { in = ch_w2;  out = o4; idx = i - 2 * N4_TW - N4_CW; }
    else return;
    float4 v = ((const float4*)in)[idx];
    __half2 h0 = __floats2half2_rn(v.x, v.y);
    __half2 h1 = __floats2half2_rn(v.z, v.w);
    stcs_v2u32((char*)out + 8 * (size_t)idx,
               *reinterpret_cast<uint32_t*>(&h0), *reinterpret_cast<uint32_t*>(&h1));
}

// ---------------- launch 3: gate + work list ---------------------------------
__global__ void gate_kernel(const float* __restrict__ rw, float* __restrict__ aux_out) {
    __shared__ float s_probs[Bq][Ee];
    __shared__ int   s_top1[Bq];
    __shared__ int   s_top2[Bq];
    int warp = threadIdx.x >> 5, lane = threadIdx.x & 31;
    int nwarp = blockDim.x >> 5;
    for (int b = warp; b < Bq; b += nwarp) {
        float logits[Ee];
        #pragma unroll
        for (int e = 0; e < Ee; e++) {
            float s = 0.f;
            for (int d = lane; d < Dd; d += 32)
                s += g_xmean[b * Dd + d] * rw[e * Dd + d];
            #pragma unroll
            for (int o = 16; o; o >>= 1) s += __shfl_xor_sync(0xffffffffu, s, o);
            logits[e] = s;
        }
        if (lane == 0) {
            float mx = logits[0];
            #pragma unroll
            for (int e = 1; e < Ee; e++) mx = fmaxf(mx, logits[e]);
            float p[Ee], se = 0.f;
            #pragma unroll
            for (int e = 0; e < Ee; e++) { p[e] = expf(logits[e] - mx); se += p[e]; }
            float inv = 1.0f / se;
            #pragma unroll
            for (int e = 0; e < Ee; e++) p[e] *= inv;
            int i0 = 0;
            #pragma unroll
            for (int e = 1; e < Ee; e++) if (p[e] > p[i0]) i0 = e;
            int i1 = (i0 == 0) ? 1 : 0;
            #pragma unroll
            for (int e = 0; e < Ee; e++) if (e != i1 && e != i0 && p[e] > p[i1]) i1 = e;
            float ws = p[i0] + p[i1];
            #pragma unroll
            for (int e = 0; e < Ee; e++) { g_combine[b * Ee + e] = 0.f; g_slot[b * Ee + e] = -1; }
            g_combine[b * Ee + i0] = p[i0] / ws;  g_slot[b * Ee + i0] = b * 2;
            g_combine[b * Ee + i1] = p[i1] / ws;  g_slot[b * Ee + i1] = b * 2 + 1;
            #pragma unroll
            for (int e = 0; e < Ee; e++) s_probs[b][e] = p[e];
            s_top1[b] = i0;
            s_top2[b] = i1;
        }
    }
    __syncthreads();
    if (threadIdx.x == 0) {
        int cnt = 0;
        for (int b = 0; b < Bq; b++)
            for (int e = 0; e < Ee; e++)
                if (e == s_top1[b] || e == s_top2[b]) g_wl[cnt++] = (b << 8) | e;
        if (aux_out != nullptr) {
            float aux = 0.f;
            for (int e = 0; e < Ee; e++) {
                float pm = 0.f; int c = 0;
                for (int b = 0; b < Bq; b++) { pm += s_probs[b][e]; c += (s_top1[b] == e); }
                aux += (pm / Bq) * ((float)c / Bq);
            }
            aux_out[0] = (float)Ee * aux;
        }
    }
}

// ---------------- launch 4 (ncu-captured): GEMM1 -----------------------------
__global__ void __launch_bounds__(256, 2) gemm1_mma(const float* __restrict__ tok_b1,
                                                    const float* __restrict__ ch_b1) {
    extern __shared__ char smem[];
    int code = g_wl[blockIdx.y];
    int b = code >> 8, eg = code & 255;
    int is_token = (eg < E_TOK);
    int el = is_token ? eg : (eg - E_TOK);
    float w = g_combine[b * Ee + eg];
    int slot = g_slot[b * Ee + eg];
    int Nh = is_token ? HN : HD;
    int K  = is_token ? Nn : Dd;
    int tilesN = Nh / BN;
    int m0 = (blockIdx.x / tilesN) * BM;
    int n0 = (blockIdx.x % tilesN) * BN;

    const __half *A, *B;
    if (is_token) {
        A = g_xt  + (size_t)b  * Dd * Nn + (size_t)m0 * Nn;
        B = g_w1t + (size_t)el * HN * Nn + (size_t)n0 * Nn;
    } else {
        A = g_xc  + (size_t)b  * Nn * Dd + (size_t)m0 * Dd;
        B = g_w1c + (size_t)el * HD * Dd + (size_t)n0 * Dd;
    }

    uint32_t sb = s2u(smem);
    int tid = threadIdx.x, wid = tid >> 5, lane = tid & 31;
    int wm = wid >> 2, wn = wid & 3;

    float acc[4][4][4] = {};
    gemm_pipeline(sb, A, B, K, acc, wm, wn, lane, tid);

    __half* H = g_hid + (size_t)slot * SLOT_STRIDE;
    const float* b1e = (is_token ? tok_b1 : ch_b1) + el * Nh;
    #pragma unroll
    for (int mf = 0; mf < 4; mf++) {
        int m = m0 + wm * 64 + mf * 16 + (lane >> 2);
        #pragma unroll
        for (int nf = 0; nf < 4; nf++) {
            int col = n0 + wn * 32 + nf * 8 + (lane & 3) * 2;
            float bv0 = b1e[col], bv1 = b1e[col + 1];
            #pragma unroll
            for (int half = 0; half < 2; half++) {
                int mm = m + half * 8;
                float v0 = w * gelu_tanh(acc[mf][nf][half * 2]     + bv0);
                float v1 = w * gelu_tanh(acc[mf][nf][half * 2 + 1] + bv1);
                __half2 hh = __floats2half2_rn(v0, v1);
                stcs_u32(H + (size_t)mm * Nh + col, *reinterpret_cast<uint32_t*>(&hh));
            }
        }
    }
}

// ---------------- launch 5: GEMM2 --------------------------------------------
__global__ void __launch_bounds__(256, 2) gemm2_mma(const float* __restrict__ tok_b2,
                                                    const float* __restrict__ ch_b2,
                                                    float* __restrict__ out) {
    extern __shared__ char smem[];
    int b = Bq - 1 - blockIdx.z;   // reversed: catch gemm1's freshest hid in L2
    int n0 = (blockIdx.x / (Dd / BN)) * BM;
    int d0 = (blockIdx.x % (Dd / BN)) * BN;

    int ae[2]; float aw[2]; int cnt = 0;
    #pragma unroll
    for (int e = 0; e < Ee; e++) {
        float wv = g_combine[b * Ee + e];
        if (wv != 0.f && cnt < 2) { ae[cnt] = e; aw[cnt] = wv; cnt++; }
    }

    uint32_t sb = s2u(smem);
    int tid = threadIdx.x, wid = tid >> 5, lane = tid & 31;
    int wm = wid >> 2, wn = wid & 3;

    float acc[4][4][4] = {};
    for (int xi = 0; xi < cnt; xi++) {
        int e = ae[xi];
        int slot = g_slot[b * Ee + e];
        const __half *A, *B;
        int K;
        if (e < E_TOK) {
            A = g_w2t + (size_t)e * Nn * HN + (size_t)n0 * HN;
            B = g_hid + (size_t)slot * SLOT_STRIDE + (size_t)d0 * HN;
            K = HN;
        } else {
            A = g_hid + (size_t)slot * SLOT_STRIDE + (size_t)n0 * HD;
            B = g_w2c + (size_t)(e - E_TOK) * Dd * HD + (size_t)d0 * HD;
            K = HD;
        }
        gemm_pipeline(sb, A, B, K, acc, wm, wn, lane, tid);
    }

    #pragma unroll
    for (int mf = 0; mf < 4; mf++) {
        int m = n0 + wm * 64 + mf * 16 + (lane >> 2);
        #pragma unroll
        for (int half = 0; half < 2; half++) {
            int mm = m + half * 8;
            float rowb = 0.f;
            #pragma unroll
            for (int xi = 0; xi < 2; xi++)
                if (xi < cnt && ae[xi] < E_TOK) rowb += aw[xi] * tok_b2[ae[xi] * Nn + mm];
            float* orow = out + ((size_t)b * Nn + mm) * Dd;
            #pragma unroll
            for (int nf = 0; nf < 4; nf++) {
                int col = d0 + wn * 32 + nf * 8 + (lane & 3) * 2;
                float cb0 = 0.f, cb1 = 0.f;
                #pragma unroll
                for (int xi = 0; xi < 2; xi++)
                    if (xi < cnt && ae[xi] >= E_TOK) {
                        const float* cb = ch_b2 + (ae[xi] - E_TOK) * Dd;
                        cb0 += aw[xi] * cb[col];
                        cb1 += aw[xi] * cb[col + 1];
                    }
                stcs_v2f32(orow + col,
                           acc[mf][nf][half * 2]     + rowb + cb0,
                           acc[mf][nf][half * 2 + 1] + rowb + cb1);
            }
        }
    }
}

// ---------------- launch -----------------------------------------------------
extern "C" void kernel_launch(void* const* d_in, const int* in_sizes, int n_in,
                              void* d_out, int out_size) {
    const float* x      = (const float*)d_in[0];
    const float* rw     = (const float*)d_in[1];
    const float* tok_w1 = (const float*)d_in[2];
    const float* tok_b1 = (const float*)d_in[3];
    const float* tok_w2 = (const float*)d_in[4];
    const float* tok_b2 = (const float*)d_in[5];
    const float* ch_w1  = (const float*)d_in[6];
    const float* ch_b1  = (const float*)d_in[7];
    const float* ch_w2  = (const float*)d_in[8];
    const float* ch_b2  = (const float*)d_in[9];
    float* out = (float*)d_out;
    (void)in_sizes; (void)n_in;
    float* auxp = (out_size > Bq * Nn * Dd) ? (out + (size_t)Bq * Nn * Dd) : nullptr;

    cudaFuncSetAttribute(gemm1_mma, cudaFuncAttributeMaxDynamicSharedMemorySize, SMEM_DYN);
    cudaFuncSetAttribute(gemm2_mma, cudaFuncAttributeMaxDynamicSharedMemorySize, SMEM_DYN);

    // launch 1: x conversion + mean partials (fused)
    xcvt_mean_kernel<<<dim3(Dd / 32, Nn / 32, Bq), dim3(32, 8)>>>(x);

    // launch 2: weight conversions + parallel mean reduce (blocks 0..31)
    {
        __half *p_w1t, *p_w2t, *p_w1c, *p_w2c;
        cudaGetSymbolAddress((void**)&p_w1t, g_w1t);
        cudaGetSymbolAddress((void**)&p_w2t, g_w2t);
        cudaGetSymbolAddress((void**)&p_w1c, g_w1c);
        cudaGetSymbolAddress((void**)&p_w2c, g_w2c);
        int n4 = 2 * (N4_TW + N4_CW);
        cvt_mean_kernel<<<Bq + (n4 + 255) / 256, 256>>>(tok_w1, tok_w2, ch_w1, ch_w2,
                                                        p_w1t, p_w2t, p_w1c, p_w2c);
    }

    // launch 3: gate + work list
    gate_kernel<<<1, 256>>>(rw, auxp);

    // launch 4 (ncu captures this one): GEMM1
    dim3 g1(192, Bq * 2);
    gemm1_mma<<<g1, 256, SMEM_DYN>>>(tok_b1, ch_b1);

    // launch 5: GEMM2
    dim3 g2((Nn / BM) * (Dd / BN), 1, Bq);
    gemm2_mma<<<g2, 256, SMEM_DYN>>>(tok_b2, ch_b2, out);
}